// round 16
// baseline (speedup 1.0000x reference)
#include <cuda_runtime.h>
#include <cuda_fp16.h>
#include <cuda_bf16.h>

#define NN 100000
#define NE 1600000
#define DD 128
#define CAP 64  // per-node adjacency capacity; deg ~ Poisson(16), P(>64) ~ 1e-20

// Scratch (device globals; allocation-free per harness rules)
__device__ __align__(16) __half g_h16[(size_t)NN * DD];   // layer-1 GEMM output
__device__ __align__(16) __half g_h16b[(size_t)NN * DD];  // layer-2 GEMM output (prescaled)
__device__ __align__(16) __half g_agg16[(size_t)NN * DD]; // layer-1 activations
__device__ float  g_dinv[NN];
__device__ __half g_dinvh[NN];
__device__ int    g_cnt[NN];                 // in-degree (excl. self-loop)
__device__ int    g_colp[(size_t)NN * CAP];  // padded adjacency rows

// ---------------- GEMM (fp16 mma.m16n8k16 + ldmatrix, 32x64 warp tiles) -----

__device__ __forceinline__ float4 ldA4(const float* A, size_t row, int c) {
    return *(const float4*)(A + row * 128 + c);
}
__device__ __forceinline__ float4 ldA4(const __half* A, size_t row, int c) {
    uint2 raw = *(const uint2*)(A + row * 128 + c);
    float2 f0 = __half22float2(*(__half2*)&raw.x);
    float2 f1 = __half22float2(*(__half2*)&raw.y);
    return make_float4(f0.x, f0.y, f1.x, f1.y);
}

__device__ __forceinline__ void mma_f16(float* d, unsigned a0, unsigned a1,
                                        unsigned a2, unsigned a3, unsigned b0,
                                        unsigned b1) {
    asm volatile(
        "mma.sync.aligned.m16n8k16.row.col.f32.f16.f16.f32 "
        "{%0,%1,%2,%3}, {%4,%5,%6,%7}, {%8,%9}, {%0,%1,%2,%3};"
        : "+f"(d[0]), "+f"(d[1]), "+f"(d[2]), "+f"(d[3])
        : "r"(a0), "r"(a1), "r"(a2), "r"(a3), "r"(b0), "r"(b1));
}

__device__ __forceinline__ void ldmx4(unsigned& r0, unsigned& r1, unsigned& r2,
                                      unsigned& r3, unsigned addr) {
    asm volatile("ldmatrix.sync.aligned.m8n8.x4.shared.b16 {%0,%1,%2,%3}, [%4];"
                 : "=r"(r0), "=r"(r1), "=r"(r2), "=r"(r3)
                 : "r"(addr));
}

#define GEMM_SMEM (2 * 128 * 136 * (int)sizeof(__half))  // 69632 B

// C[M,128] = A[M,128] @ W[128,128]; fp16 inputs, fp32 accumulate.
// SCALE: multiply row r of C by g_dinv[r] (fp32) before the fp16 store.
template <typename T, bool SCALE>
__global__ void __launch_bounds__(256) k_gemm(const T* __restrict__ A,
                                              const float* __restrict__ W,
                                              __half* __restrict__ H, int M) {
    extern __shared__ __half sm[];
    __half(*As)[136] = (__half(*)[136])sm;                 // [m][k]
    __half(*Bs)[136] = (__half(*)[136])(sm + 128 * 136);   // [n][k] (W^T)

    const int tid = threadIdx.x;
    const int warp = tid >> 5;
    const int lane = tid & 31;
    const int gid = lane >> 2;  // 0..7
    const int tq = lane & 3;    // 0..3
    const int row0 = blockIdx.x * 128;
    const int wr = warp & 3;    // warp row (4)
    const int wc = warp >> 2;   // warp col (2)

#pragma unroll
    for (int it = 0; it < 16; it++) {
        int idx = tid + it * 256;
        int r = idx >> 5;
        int c4 = (idx & 31) * 4;
        int gm = row0 + r;
        __half2 p0 = __floats2half2_rn(0.f, 0.f), p1 = p0;
        if (gm < M) {
            float4 v = ldA4(A, (size_t)gm, c4);
            p0 = __floats2half2_rn(v.x, v.y);
            p1 = __floats2half2_rn(v.z, v.w);
        }
        uint2 st;
        st.x = *(unsigned*)&p0;
        st.y = *(unsigned*)&p1;
        *(uint2*)&As[r][c4] = st;
    }
#pragma unroll
    for (int it = 0; it < 32; it++) {
        int g = tid + it * 256;
        int k2 = g >> 7;
        int n = g & 127;
        float w0 = __ldg(W + (size_t)(2 * k2) * 128 + n);
        float w1 = __ldg(W + (size_t)(2 * k2 + 1) * 128 + n);
        *(__half2*)&Bs[n][2 * k2] = __floats2half2_rn(w0, w1);
    }
    __syncthreads();

    float d[2][8][4];
#pragma unroll
    for (int i = 0; i < 2; i++)
#pragma unroll
        for (int nt = 0; nt < 8; nt++)
#pragma unroll
            for (int j = 0; j < 4; j++) d[i][nt][j] = 0.f;

    const unsigned aAddr0 = (unsigned)__cvta_generic_to_shared(
        &As[32 * wr + (lane & 15)][8 * (lane >> 4)]);
    const unsigned aAddr1 = aAddr0 + 16 * 136 * 2;  // +16 rows
    const int grp = lane >> 3;
    const unsigned bAddr = (unsigned)__cvta_generic_to_shared(
        &Bs[64 * wc + (grp >> 1) * 8 + (lane & 7)][(grp & 1) * 8]);

#pragma unroll
    for (int ks = 0; ks < 8; ks++) {
        int k0 = ks * 16;
        unsigned a00, a01, a02, a03, a10, a11, a12, a13;
        ldmx4(a00, a01, a02, a03, aAddr0 + k0 * 2);
        ldmx4(a10, a11, a12, a13, aAddr1 + k0 * 2);
#pragma unroll
        for (int p = 0; p < 4; p++) {
            unsigned b0, b1, b2, b3;
            ldmx4(b0, b1, b2, b3, bAddr + (p * 16 * 136 + k0) * 2);
            mma_f16(d[0][2 * p],     a00, a01, a02, a03, b0, b1);
            mma_f16(d[0][2 * p + 1], a00, a01, a02, a03, b2, b3);
            mma_f16(d[1][2 * p],     a10, a11, a12, a13, b0, b1);
            mma_f16(d[1][2 * p + 1], a10, a11, a12, a13, b2, b3);
        }
    }

#pragma unroll
    for (int i = 0; i < 2; i++) {
        int r0 = row0 + 32 * wr + 16 * i + gid;
        int r1 = r0 + 8;
        float s0 = 1.f, s1 = 1.f;
        if (SCALE) {
            if (r0 < M) s0 = g_dinv[r0];
            if (r1 < M) s1 = g_dinv[r1];
        }
#pragma unroll
        for (int nt = 0; nt < 8; nt++) {
            int c = 64 * wc + 8 * nt + 2 * tq;
            if (r0 < M)
                *(__half2*)(H + (size_t)r0 * 128 + c) =
                    __floats2half2_rn(d[i][nt][0] * s0, d[i][nt][1] * s0);
            if (r1 < M)
                *(__half2*)(H + (size_t)r1 * 128 + c) =
                    __floats2half2_rn(d[i][nt][2] * s1, d[i][nt][3] * s1);
        }
    }
}

// Side stream + events + smem opt-in (static init, before harness checkpoints).
static cudaStream_t g_s2;
static cudaEvent_t g_evF, g_evJ;
namespace {
struct StreamInit {
    StreamInit() {
        cudaStreamCreateWithFlags(&g_s2, cudaStreamNonBlocking);
        cudaEventCreateWithFlags(&g_evF, cudaEventDisableTiming);
        cudaEventCreateWithFlags(&g_evJ, cudaEventDisableTiming);
        cudaFuncSetAttribute((const void*)k_gemm<float, false>,
                             cudaFuncAttributeMaxDynamicSharedMemorySize, GEMM_SMEM);
        cudaFuncSetAttribute((const void*)k_gemm<__half, true>,
                             cudaFuncAttributeMaxDynamicSharedMemorySize, GEMM_SMEM);
    }
};
StreamInit g_si;
}  // namespace

// ---------------- direct-fill padded CSR ----------------

__global__ void k_fill_direct(const int* __restrict__ src,
                              const int* __restrict__ dst) {
    int e = (blockIdx.x * blockDim.x + threadIdx.x) * 4;  // NE % 4 == 0
    if (e < NE) {
        int4 s = *(const int4*)(src + e);
        int4 d = *(const int4*)(dst + e);
        int p;
        p = atomicAdd(&g_cnt[d.x], 1); if (p < CAP) g_colp[(size_t)d.x * CAP + p] = s.x;
        p = atomicAdd(&g_cnt[d.y], 1); if (p < CAP) g_colp[(size_t)d.y * CAP + p] = s.y;
        p = atomicAdd(&g_cnt[d.z], 1); if (p < CAP) g_colp[(size_t)d.z * CAP + p] = s.z;
        p = atomicAdd(&g_cnt[d.w], 1); if (p < CAP) g_colp[(size_t)d.w * CAP + p] = s.w;
    }
}

__global__ void k_dinv() {
    int i = blockIdx.x * blockDim.x + threadIdx.x;
    if (i < NN) {
        float d = rsqrtf((float)(g_cnt[i] + 1));  // +1 self-loop
        g_dinv[i] = d;
        g_dinvh[i] = __float2half_rn(d);
    }
}

// ---------------- gather (software-pipelined, 64-thread blocks) ----------------
// PRESCALED=false: out[w] = relu(dinv[w]*(dinv[w]*h[w] + sum dinv[s]*h[s]) + b)
// PRESCALED=true  (h already = dinv*C): out[w] = relu(dinv[w]*(h[w] + sum h[s]) + b)

__device__ __forceinline__ __half2 h2(unsigned u) { return *(__half2*)&u; }

__device__ __forceinline__ void fma_h4(float4& a, uint2 raw, float s) {
    float2 f0 = __half22float2(*(__half2*)&raw.x);
    float2 f1 = __half22float2(*(__half2*)&raw.y);
    a.x = fmaf(f0.x, s, a.x);
    a.y = fmaf(f0.y, s, a.y);
    a.z = fmaf(f1.x, s, a.z);
    a.w = fmaf(f1.y, s, a.w);
}
__device__ __forceinline__ void add_h4(float4& a, uint2 raw) {
    float2 f0 = __half22float2(*(__half2*)&raw.x);
    float2 f1 = __half22float2(*(__half2*)&raw.y);
    a.x += f0.x; a.y += f0.y; a.z += f1.x; a.w += f1.y;
}
__device__ __forceinline__ void flush_h2(float4& a, __half2 sx, __half2 sy) {
    float2 f0 = __half22float2(sx);
    float2 f1 = __half22float2(sy);
    a.x += f0.x; a.y += f0.y; a.z += f1.x; a.w += f1.y;
}

template <bool PRESCALED>
struct Grp8 {
    uint2 r[8];
    __half dv[8];
    __device__ __forceinline__ void load(const uint2* H, const int* col, int e,
                                         int lane) {
        int4 ca = *(const int4*)(col + e);
        int4 cb = *(const int4*)(col + e + 4);
        r[0] = H[(size_t)ca.x * 32 + lane];
        r[1] = H[(size_t)ca.y * 32 + lane];
        r[2] = H[(size_t)ca.z * 32 + lane];
        r[3] = H[(size_t)ca.w * 32 + lane];
        r[4] = H[(size_t)cb.x * 32 + lane];
        r[5] = H[(size_t)cb.y * 32 + lane];
        r[6] = H[(size_t)cb.z * 32 + lane];
        r[7] = H[(size_t)cb.w * 32 + lane];
        if (!PRESCALED) {
            dv[0] = g_dinvh[ca.x]; dv[1] = g_dinvh[ca.y];
            dv[2] = g_dinvh[ca.z]; dv[3] = g_dinvh[ca.w];
            dv[4] = g_dinvh[cb.x]; dv[5] = g_dinvh[cb.y];
            dv[6] = g_dinvh[cb.z]; dv[7] = g_dinvh[cb.w];
        }
    }
    __device__ __forceinline__ void flush(float4& acc, float4& acc2) const {
        if (PRESCALED) {
            __half2 sxA = __hadd2(__hadd2(h2(r[0].x), h2(r[1].x)),
                                  __hadd2(h2(r[2].x), h2(r[3].x)));
            __half2 syA = __hadd2(__hadd2(h2(r[0].y), h2(r[1].y)),
                                  __hadd2(h2(r[2].y), h2(r[3].y)));
            flush_h2(acc, sxA, syA);
            __half2 sxB = __hadd2(__hadd2(h2(r[4].x), h2(r[5].x)),
                                  __hadd2(h2(r[6].x), h2(r[7].x)));
            __half2 syB = __hadd2(__hadd2(h2(r[4].y), h2(r[5].y)),
                                  __hadd2(h2(r[6].y), h2(r[7].y)));
            flush_h2(acc2, sxB, syB);
        } else {
            __half2 d0 = __half2half2(dv[0]), d1 = __half2half2(dv[1]);
            __half2 d2 = __half2half2(dv[2]), d3 = __half2half2(dv[3]);
            __half2 d4 = __half2half2(dv[4]), d5 = __half2half2(dv[5]);
            __half2 d6 = __half2half2(dv[6]), d7 = __half2half2(dv[7]);
            __half2 sxA = __hadd2(__hfma2(h2(r[0].x), d0, __hmul2(h2(r[1].x), d1)),
                                  __hfma2(h2(r[2].x), d2, __hmul2(h2(r[3].x), d3)));
            __half2 syA = __hadd2(__hfma2(h2(r[0].y), d0, __hmul2(h2(r[1].y), d1)),
                                  __hfma2(h2(r[2].y), d2, __hmul2(h2(r[3].y), d3)));
            flush_h2(acc, sxA, syA);
            __half2 sxB = __hadd2(__hfma2(h2(r[4].x), d4, __hmul2(h2(r[5].x), d5)),
                                  __hfma2(h2(r[6].x), d6, __hmul2(h2(r[7].x), d7)));
            __half2 syB = __hadd2(__hfma2(h2(r[4].y), d4, __hmul2(h2(r[5].y), d5)),
                                  __hfma2(h2(r[6].y), d6, __hmul2(h2(r[7].y), d7)));
            flush_h2(acc2, sxB, syB);
        }
    }
};

template <bool OUT_HALF, bool PRESCALED>
__global__ void __launch_bounds__(64) k_gather(const __half* __restrict__ h,
                                               const float* __restrict__ bias,
                                               void* __restrict__ outv) {
    int w = (blockIdx.x * 64 + threadIdx.x) >> 5;  // node
    int lane = threadIdx.x & 31;
    if (w >= NN) return;
    int n = min(g_cnt[w], CAP);
    const int* col = g_colp + (size_t)w * CAP;
    const uint2* H = (const uint2*)h;  // 8B per lane: 4 halves
    float dw = g_dinv[w];
    float4 acc = make_float4(0.f, 0.f, 0.f, 0.f);
    if (PRESCALED) add_h4(acc, H[(size_t)w * 32 + lane]);
    else           fma_h4(acc, H[(size_t)w * 32 + lane], dw);
    float4 acc2 = make_float4(0.f, 0.f, 0.f, 0.f);
    int e = 0;
    if (n >= 8) {
        Grp8<PRESCALED> cur, nxt;
        cur.load(H, col, 0, lane);
        for (e = 8; e + 8 <= n; e += 8) {
            nxt.load(H, col, e, lane);  // next group's loads issued BEFORE flush
            cur.flush(acc, acc2);
            cur = nxt;
        }
        cur.flush(acc, acc2);
    }
    // tail: exact fp32 path
    for (; e < n; e++) {
        int s = __ldg(&col[e]);
        if (PRESCALED) add_h4(acc, H[(size_t)s * 32 + lane]);
        else           fma_h4(acc, H[(size_t)s * 32 + lane], __ldg(&g_dinv[s]));
    }
    acc.x += acc2.x; acc.y += acc2.y; acc.z += acc2.z; acc.w += acc2.w;
    float4 b = ((const float4*)bias)[lane];
    float4 o;
    o.x = fmaxf(fmaf(acc.x, dw, b.x), 0.f);
    o.y = fmaxf(fmaf(acc.y, dw, b.y), 0.f);
    o.z = fmaxf(fmaf(acc.z, dw, b.z), 0.f);
    o.w = fmaxf(fmaf(acc.w, dw, b.w), 0.f);
    if (OUT_HALF) {
        __half2 p0 = __floats2half2_rn(o.x, o.y);
        __half2 p1 = __floats2half2_rn(o.z, o.w);
        uint2 r;
        r.x = *(unsigned*)&p0;
        r.y = *(unsigned*)&p1;
        ((uint2*)outv)[(size_t)w * 32 + lane] = r;
    } else {
        ((float4*)outv)[(size_t)w * 32 + lane] = o;
    }
}

// ---------------- launch ----------------

extern "C" void kernel_launch(void* const* d_in, const int* in_sizes, int n_in,
                              void* d_out, int out_size) {
    const float* x  = (const float*)d_in[0];
    const int*   ei = (const int*)d_in[1];
    const float* W1 = (const float*)d_in[2];
    const float* b1 = (const float*)d_in[3];
    const float* W2 = (const float*)d_in[4];
    const float* b2 = (const float*)d_in[5];
    const int* src = ei;
    const int* dst = ei + NE;
    float* out = (float*)d_out;

    cudaFuncSetAttribute((const void*)k_gemm<float, false>,
                         cudaFuncAttributeMaxDynamicSharedMemorySize, GEMM_SMEM);
    cudaFuncSetAttribute((const void*)k_gemm<__half, true>,
                         cudaFuncAttributeMaxDynamicSharedMemorySize, GEMM_SMEM);

    __half *hbuf = nullptr, *hbuf2 = nullptr, *aggbuf = nullptr;
    int* cntp = nullptr;
    cudaGetSymbolAddress((void**)&hbuf, g_h16);
    cudaGetSymbolAddress((void**)&hbuf2, g_h16b);
    cudaGetSymbolAddress((void**)&aggbuf, g_agg16);
    cudaGetSymbolAddress((void**)&cntp, g_cnt);

    const int TB = 256;
    const int gemmBlocks = (NN + 127) / 128;            // 782
    const int gatherBlocks = (NN * 32 + 63) / 64;       // 50000 (64-thr blocks)
    const int e4Blocks = (NE / 4 + TB - 1) / TB;        // 1563 (ceil)

    // ---- fork: padded-CSR build on side stream, GEMM1 on main stream ----
    cudaEventRecord(g_evF, 0);
    cudaStreamWaitEvent(g_s2, g_evF, 0);
    cudaMemsetAsync(cntp, 0, NN * sizeof(int), g_s2);
    k_fill_direct<<<e4Blocks, TB, 0, g_s2>>>(src, dst);                     // #1
    k_dinv<<<(NN + TB - 1) / TB, TB, 0, g_s2>>>();                          // #2
    cudaEventRecord(g_evJ, g_s2);

    k_gemm<float, false><<<gemmBlocks, 256, GEMM_SMEM>>>(x, W1, hbuf, NN);  // #3

    // ---- join, then monolithic pipeline ----
    cudaStreamWaitEvent(0, g_evJ, 0);
    k_gather<true, false><<<gatherBlocks, 64>>>(hbuf, b1, aggbuf);          // #4 (profiled)
    k_gemm<__half, true><<<gemmBlocks, 256, GEMM_SMEM>>>(aggbuf, W2, hbuf2, NN);  // #5
    k_gather<false, true><<<gatherBlocks, 64>>>(hbuf2, b2, out);            // #6
}

// round 17
// speedup vs baseline: 1.1886x; 1.1886x over previous
#include <cuda_runtime.h>
#include <cuda_fp16.h>
#include <cuda_bf16.h>

#define NN 100000
#define NE 1600000
#define DD 128
#define CAP 64  // per-node adjacency capacity; deg ~ Poisson(16), P(>64) ~ 1e-20

// Scratch (device globals; allocation-free per harness rules)
__device__ __align__(16) __half g_h16[(size_t)NN * DD];   // layer-1 GEMM output
__device__ __align__(16) __half g_h16b[(size_t)NN * DD];  // layer-2 GEMM output (prescaled)
__device__ __align__(16) __half g_agg16[(size_t)NN * DD]; // layer-1 activations
__device__ float  g_dinv[NN];
__device__ __half g_dinvh[NN];
__device__ int    g_cnt[NN];                 // in-degree (excl. self-loop)
__device__ int    g_colp[(size_t)NN * CAP];  // padded adjacency rows

// ---------------- GEMM (fp16 mma.m16n8k16 + ldmatrix, 32x64 warp tiles) -----

__device__ __forceinline__ float4 ldA4(const float* A, size_t row, int c) {
    return *(const float4*)(A + row * 128 + c);
}
__device__ __forceinline__ float4 ldA4(const __half* A, size_t row, int c) {
    uint2 raw = *(const uint2*)(A + row * 128 + c);
    float2 f0 = __half22float2(*(__half2*)&raw.x);
    float2 f1 = __half22float2(*(__half2*)&raw.y);
    return make_float4(f0.x, f0.y, f1.x, f1.y);
}

__device__ __forceinline__ void mma_f16(float* d, unsigned a0, unsigned a1,
                                        unsigned a2, unsigned a3, unsigned b0,
                                        unsigned b1) {
    asm volatile(
        "mma.sync.aligned.m16n8k16.row.col.f32.f16.f16.f32 "
        "{%0,%1,%2,%3}, {%4,%5,%6,%7}, {%8,%9}, {%0,%1,%2,%3};"
        : "+f"(d[0]), "+f"(d[1]), "+f"(d[2]), "+f"(d[3])
        : "r"(a0), "r"(a1), "r"(a2), "r"(a3), "r"(b0), "r"(b1));
}

__device__ __forceinline__ void ldmx4(unsigned& r0, unsigned& r1, unsigned& r2,
                                      unsigned& r3, unsigned addr) {
    asm volatile("ldmatrix.sync.aligned.m8n8.x4.shared.b16 {%0,%1,%2,%3}, [%4];"
                 : "=r"(r0), "=r"(r1), "=r"(r2), "=r"(r3)
                 : "r"(addr));
}

#define GEMM_SMEM (2 * 128 * 136 * (int)sizeof(__half))  // 69632 B

// C[M,128] = A[M,128] @ W[128,128]; fp16 inputs, fp32 accumulate.
// SCALE: multiply row r of C by g_dinv[r] (fp32) before the fp16 store.
template <typename T, bool SCALE>
__global__ void __launch_bounds__(256) k_gemm(const T* __restrict__ A,
                                              const float* __restrict__ W,
                                              __half* __restrict__ H, int M) {
    extern __shared__ __half sm[];
    __half(*As)[136] = (__half(*)[136])sm;                 // [m][k]
    __half(*Bs)[136] = (__half(*)[136])(sm + 128 * 136);   // [n][k] (W^T)

    const int tid = threadIdx.x;
    const int warp = tid >> 5;
    const int lane = tid & 31;
    const int gid = lane >> 2;  // 0..7
    const int tq = lane & 3;    // 0..3
    const int row0 = blockIdx.x * 128;
    const int wr = warp & 3;    // warp row (4)
    const int wc = warp >> 2;   // warp col (2)

#pragma unroll
    for (int it = 0; it < 16; it++) {
        int idx = tid + it * 256;
        int r = idx >> 5;
        int c4 = (idx & 31) * 4;
        int gm = row0 + r;
        __half2 p0 = __floats2half2_rn(0.f, 0.f), p1 = p0;
        if (gm < M) {
            float4 v = ldA4(A, (size_t)gm, c4);
            p0 = __floats2half2_rn(v.x, v.y);
            p1 = __floats2half2_rn(v.z, v.w);
        }
        uint2 st;
        st.x = *(unsigned*)&p0;
        st.y = *(unsigned*)&p1;
        *(uint2*)&As[r][c4] = st;
    }
#pragma unroll
    for (int it = 0; it < 32; it++) {
        int g = tid + it * 256;
        int k2 = g >> 7;
        int n = g & 127;
        float w0 = __ldg(W + (size_t)(2 * k2) * 128 + n);
        float w1 = __ldg(W + (size_t)(2 * k2 + 1) * 128 + n);
        *(__half2*)&Bs[n][2 * k2] = __floats2half2_rn(w0, w1);
    }
    __syncthreads();

    float d[2][8][4];
#pragma unroll
    for (int i = 0; i < 2; i++)
#pragma unroll
        for (int nt = 0; nt < 8; nt++)
#pragma unroll
            for (int j = 0; j < 4; j++) d[i][nt][j] = 0.f;

    const unsigned aAddr0 = (unsigned)__cvta_generic_to_shared(
        &As[32 * wr + (lane & 15)][8 * (lane >> 4)]);
    const unsigned aAddr1 = aAddr0 + 16 * 136 * 2;  // +16 rows
    const int grp = lane >> 3;
    const unsigned bAddr = (unsigned)__cvta_generic_to_shared(
        &Bs[64 * wc + (grp >> 1) * 8 + (lane & 7)][(grp & 1) * 8]);

#pragma unroll
    for (int ks = 0; ks < 8; ks++) {
        int k0 = ks * 16;
        unsigned a00, a01, a02, a03, a10, a11, a12, a13;
        ldmx4(a00, a01, a02, a03, aAddr0 + k0 * 2);
        ldmx4(a10, a11, a12, a13, aAddr1 + k0 * 2);
#pragma unroll
        for (int p = 0; p < 4; p++) {
            unsigned b0, b1, b2, b3;
            ldmx4(b0, b1, b2, b3, bAddr + (p * 16 * 136 + k0) * 2);
            mma_f16(d[0][2 * p],     a00, a01, a02, a03, b0, b1);
            mma_f16(d[0][2 * p + 1], a00, a01, a02, a03, b2, b3);
            mma_f16(d[1][2 * p],     a10, a11, a12, a13, b0, b1);
            mma_f16(d[1][2 * p + 1], a10, a11, a12, a13, b2, b3);
        }
    }

#pragma unroll
    for (int i = 0; i < 2; i++) {
        int r0 = row0 + 32 * wr + 16 * i + gid;
        int r1 = r0 + 8;
        float s0 = 1.f, s1 = 1.f;
        if (SCALE) {
            if (r0 < M) s0 = g_dinv[r0];
            if (r1 < M) s1 = g_dinv[r1];
        }
#pragma unroll
        for (int nt = 0; nt < 8; nt++) {
            int c = 64 * wc + 8 * nt + 2 * tq;
            if (r0 < M)
                *(__half2*)(H + (size_t)r0 * 128 + c) =
                    __floats2half2_rn(d[i][nt][0] * s0, d[i][nt][1] * s0);
            if (r1 < M)
                *(__half2*)(H + (size_t)r1 * 128 + c) =
                    __floats2half2_rn(d[i][nt][2] * s1, d[i][nt][3] * s1);
        }
    }
}

// Side stream + events + smem opt-in (static init, before harness checkpoints).
static cudaStream_t g_s2;
static cudaEvent_t g_evF, g_evJ;
namespace {
struct StreamInit {
    StreamInit() {
        cudaStreamCreateWithFlags(&g_s2, cudaStreamNonBlocking);
        cudaEventCreateWithFlags(&g_evF, cudaEventDisableTiming);
        cudaEventCreateWithFlags(&g_evJ, cudaEventDisableTiming);
        cudaFuncSetAttribute((const void*)k_gemm<float, false>,
                             cudaFuncAttributeMaxDynamicSharedMemorySize, GEMM_SMEM);
        cudaFuncSetAttribute((const void*)k_gemm<__half, true>,
                             cudaFuncAttributeMaxDynamicSharedMemorySize, GEMM_SMEM);
    }
};
StreamInit g_si;
}  // namespace

// ---------------- direct-fill padded CSR ----------------

__global__ void k_fill_direct(const int* __restrict__ src,
                              const int* __restrict__ dst) {
    int e = (blockIdx.x * blockDim.x + threadIdx.x) * 4;  // NE % 4 == 0
    if (e < NE) {
        int4 s = *(const int4*)(src + e);
        int4 d = *(const int4*)(dst + e);
        int p;
        p = atomicAdd(&g_cnt[d.x], 1); if (p < CAP) g_colp[(size_t)d.x * CAP + p] = s.x;
        p = atomicAdd(&g_cnt[d.y], 1); if (p < CAP) g_colp[(size_t)d.y * CAP + p] = s.y;
        p = atomicAdd(&g_cnt[d.z], 1); if (p < CAP) g_colp[(size_t)d.z * CAP + p] = s.z;
        p = atomicAdd(&g_cnt[d.w], 1); if (p < CAP) g_colp[(size_t)d.w * CAP + p] = s.w;
    }
}

__global__ void k_dinv() {
    int i = blockIdx.x * blockDim.x + threadIdx.x;
    if (i < NN) {
        float d = rsqrtf((float)(g_cnt[i] + 1));  // +1 self-loop
        g_dinv[i] = d;
        g_dinvh[i] = __float2half_rn(d);
    }
}

// ---------------- gather: TWO nodes per warp, 16 lanes per node -------------
// Lane group g (0/1) of each warp owns node 2*pair+g; each lane covers 16B
// (8 halves, uint4). Every warp instruction processes 2 edges -> half the
// per-edge issue cost, and 2 independent dep chains per warp for MLP.
// PRESCALED=false: out[w] = relu(dinv[w]*(dinv[w]*h[w] + sum dinv[s]*h[s]) + b)
// PRESCALED=true  (h already = dinv*C): out[w] = relu(dinv[w]*(h[w] + sum h[s]) + b)

__device__ __forceinline__ __half2 h2(unsigned u) { return *(__half2*)&u; }

__device__ __forceinline__ void addcvt8(float* a, uint4 raw) {
    float2 f;
    f = __half22float2(h2(raw.x)); a[0] += f.x; a[1] += f.y;
    f = __half22float2(h2(raw.y)); a[2] += f.x; a[3] += f.y;
    f = __half22float2(h2(raw.z)); a[4] += f.x; a[5] += f.y;
    f = __half22float2(h2(raw.w)); a[6] += f.x; a[7] += f.y;
}
__device__ __forceinline__ void fmacvt8(float* a, uint4 raw, float s) {
    float2 f;
    f = __half22float2(h2(raw.x)); a[0] = fmaf(f.x, s, a[0]); a[1] = fmaf(f.y, s, a[1]);
    f = __half22float2(h2(raw.y)); a[2] = fmaf(f.x, s, a[2]); a[3] = fmaf(f.y, s, a[3]);
    f = __half22float2(h2(raw.z)); a[4] = fmaf(f.x, s, a[4]); a[5] = fmaf(f.y, s, a[5]);
    f = __half22float2(h2(raw.w)); a[6] = fmaf(f.x, s, a[6]); a[7] = fmaf(f.y, s, a[7]);
}
__device__ __forceinline__ void flush2(float* a, __half2 s) {
    float2 f = __half22float2(s);
    a[0] += f.x; a[1] += f.y;
}

template <bool OUT_HALF, bool PRESCALED>
__global__ void __launch_bounds__(256) k_gather(const __half* __restrict__ h,
                                                const float* __restrict__ bias,
                                                void* __restrict__ outv) {
    int pair = blockIdx.x * 8 + (threadIdx.x >> 5);  // warp -> node pair
    int lane = threadIdx.x & 31;
    int g = lane >> 4;   // 0/1: which node of the pair
    int hl = lane & 15;  // lane within the 16-group (16B chunk index)
    int w = pair * 2 + g;
    if (w >= NN) return;  // NN even: exact
    int n = min(g_cnt[w], CAP);
    const int* col = g_colp + (size_t)w * CAP;
    const uint4* H = (const uint4*)h;  // 16B per lane: 8 halves
    float dw = g_dinv[w];
    float a[8];
#pragma unroll
    for (int i = 0; i < 8; i++) a[i] = 0.f;
    // self-loop
    {
        uint4 raw = H[(size_t)w * 16 + hl];
        if (PRESCALED) addcvt8(a, raw);
        else           fmacvt8(a, raw, dw);
    }
    int e = 0;
    for (; e + 4 <= n; e += 4) {
        int4 ca = *(const int4*)(col + e);
        uint4 r0 = H[(size_t)ca.x * 16 + hl];
        uint4 r1 = H[(size_t)ca.y * 16 + hl];
        uint4 r2 = H[(size_t)ca.z * 16 + hl];
        uint4 r3 = H[(size_t)ca.w * 16 + hl];
        if (PRESCALED) {
            flush2(a + 0, __hadd2(__hadd2(h2(r0.x), h2(r1.x)), __hadd2(h2(r2.x), h2(r3.x))));
            flush2(a + 2, __hadd2(__hadd2(h2(r0.y), h2(r1.y)), __hadd2(h2(r2.y), h2(r3.y))));
            flush2(a + 4, __hadd2(__hadd2(h2(r0.z), h2(r1.z)), __hadd2(h2(r2.z), h2(r3.z))));
            flush2(a + 6, __hadd2(__hadd2(h2(r0.w), h2(r1.w)), __hadd2(h2(r2.w), h2(r3.w))));
        } else {
            __half2 d0 = __half2half2(g_dinvh[ca.x]);
            __half2 d1 = __half2half2(g_dinvh[ca.y]);
            __half2 d2 = __half2half2(g_dinvh[ca.z]);
            __half2 d3 = __half2half2(g_dinvh[ca.w]);
            flush2(a + 0, __hadd2(__hfma2(h2(r0.x), d0, __hmul2(h2(r1.x), d1)),
                                  __hfma2(h2(r2.x), d2, __hmul2(h2(r3.x), d3))));
            flush2(a + 2, __hadd2(__hfma2(h2(r0.y), d0, __hmul2(h2(r1.y), d1)),
                                  __hfma2(h2(r2.y), d2, __hmul2(h2(r3.y), d3))));
            flush2(a + 4, __hadd2(__hfma2(h2(r0.z), d0, __hmul2(h2(r1.z), d1)),
                                  __hfma2(h2(r2.z), d2, __hmul2(h2(r3.z), d3))));
            flush2(a + 6, __hadd2(__hfma2(h2(r0.w), d0, __hmul2(h2(r1.w), d1)),
                                  __hfma2(h2(r2.w), d2, __hmul2(h2(r3.w), d3))));
        }
    }
    // tail: exact fp32 path
    for (; e < n; e++) {
        int s = __ldg(&col[e]);
        uint4 raw = H[(size_t)s * 16 + hl];
        if (PRESCALED) addcvt8(a, raw);
        else           fmacvt8(a, raw, __ldg(&g_dinv[s]));
    }
    float4 b0 = ((const float4*)bias)[hl * 2];
    float4 b1 = ((const float4*)bias)[hl * 2 + 1];
    float o[8];
    o[0] = fmaxf(fmaf(a[0], dw, b0.x), 0.f);
    o[1] = fmaxf(fmaf(a[1], dw, b0.y), 0.f);
    o[2] = fmaxf(fmaf(a[2], dw, b0.z), 0.f);
    o[3] = fmaxf(fmaf(a[3], dw, b0.w), 0.f);
    o[4] = fmaxf(fmaf(a[4], dw, b1.x), 0.f);
    o[5] = fmaxf(fmaf(a[5], dw, b1.y), 0.f);
    o[6] = fmaxf(fmaf(a[6], dw, b1.z), 0.f);
    o[7] = fmaxf(fmaf(a[7], dw, b1.w), 0.f);
    if (OUT_HALF) {
        __half2 p0 = __floats2half2_rn(o[0], o[1]);
        __half2 p1 = __floats2half2_rn(o[2], o[3]);
        __half2 p2 = __floats2half2_rn(o[4], o[5]);
        __half2 p3 = __floats2half2_rn(o[6], o[7]);
        uint4 r;
        r.x = *(unsigned*)&p0;
        r.y = *(unsigned*)&p1;
        r.z = *(unsigned*)&p2;
        r.w = *(unsigned*)&p3;
        ((uint4*)outv)[(size_t)w * 16 + hl] = r;
    } else {
        ((float4*)outv)[(size_t)w * 32 + hl * 2]     = make_float4(o[0], o[1], o[2], o[3]);
        ((float4*)outv)[(size_t)w * 32 + hl * 2 + 1] = make_float4(o[4], o[5], o[6], o[7]);
    }
}

// ---------------- launch ----------------

extern "C" void kernel_launch(void* const* d_in, const int* in_sizes, int n_in,
                              void* d_out, int out_size) {
    const float* x  = (const float*)d_in[0];
    const int*   ei = (const int*)d_in[1];
    const float* W1 = (const float*)d_in[2];
    const float* b1 = (const float*)d_in[3];
    const float* W2 = (const float*)d_in[4];
    const float* b2 = (const float*)d_in[5];
    const int* src = ei;
    const int* dst = ei + NE;
    float* out = (float*)d_out;

    cudaFuncSetAttribute((const void*)k_gemm<float, false>,
                         cudaFuncAttributeMaxDynamicSharedMemorySize, GEMM_SMEM);
    cudaFuncSetAttribute((const void*)k_gemm<__half, true>,
                         cudaFuncAttributeMaxDynamicSharedMemorySize, GEMM_SMEM);

    __half *hbuf = nullptr, *hbuf2 = nullptr, *aggbuf = nullptr;
    int* cntp = nullptr;
    cudaGetSymbolAddress((void**)&hbuf, g_h16);
    cudaGetSymbolAddress((void**)&hbuf2, g_h16b);
    cudaGetSymbolAddress((void**)&aggbuf, g_agg16);
    cudaGetSymbolAddress((void**)&cntp, g_cnt);

    const int TB = 256;
    const int gemmBlocks = (NN + 127) / 128;          // 782
    const int gatherBlocks = (NN / 2 + 7) / 8;        // 6250 (2 nodes/warp, 8 warps/blk)
    const int e4Blocks = (NE / 4 + TB - 1) / TB;      // 1563 (ceil)

    // ---- fork: padded-CSR build on side stream, GEMM1 on main stream ----
    cudaEventRecord(g_evF, 0);
    cudaStreamWaitEvent(g_s2, g_evF, 0);
    cudaMemsetAsync(cntp, 0, NN * sizeof(int), g_s2);
    k_fill_direct<<<e4Blocks, TB, 0, g_s2>>>(src, dst);                     // #1
    k_dinv<<<(NN + TB - 1) / TB, TB, 0, g_s2>>>();                          // #2
    cudaEventRecord(g_evJ, g_s2);

    k_gemm<float, false><<<gemmBlocks, 256, GEMM_SMEM>>>(x, W1, hbuf, NN);  // #3

    // ---- join, then monolithic pipeline ----
    cudaStreamWaitEvent(0, g_evJ, 0);
    k_gather<true, false><<<gatherBlocks, TB>>>(hbuf, b1, aggbuf);          // #4 (profiled)
    k_gemm<__half, true><<<gemmBlocks, 256, GEMM_SMEM>>>(aggbuf, W2, hbuf2, NN);  // #5
    k_gather<false, true><<<gatherBlocks, TB>>>(hbuf2, b2, out);            // #6
}